// round 2
// baseline (speedup 1.0000x reference)
#include <cuda_runtime.h>

#define N_NODES 25000
#define N_EDGES 320000
#define F       64
#define NHEADS  5
#define NRELS   20
#define NBASES  10
#define OUTC    320   // NHEADS * F

// ---------------- static device scratch (no allocations) -------------------
__device__ float  g_z[N_NODES * F];                  // 6.4 MB projected z
__device__ float4 g_attn4[NRELS * NHEADS * 32];      // packed (ws0,ws1,wd0,wd1) per lane
__device__ int    g_cnt[N_NODES];
__device__ int    g_off[N_NODES + 1];
__device__ int    g_cur[N_NODES];
__device__ int    g_eidx[N_EDGES];

// ---------------------------------------------------------------------------
// Kernel A: fused projection GEMM:  feat @ [fc_w | self_fc_w]
// cols 0..63 -> g_z ; cols 64..383 -> d_out (self_z, re-inits output)
// 128x128 block tile, K=64, 256 threads, 8x8 microtile.
// ---------------------------------------------------------------------------
__global__ void __launch_bounds__(256) proj_kernel(const float* __restrict__ feat,
                                                   const float* __restrict__ fc_w,
                                                   const float* __restrict__ self_fc_w,
                                                   float* __restrict__ out)
{
    __shared__ float As[128][65];   // [row][k]
    __shared__ float Bs[64][132];   // [k][col] (132*4B = 16B-aligned rows)

    const int tid = threadIdx.x;
    const int m0  = blockIdx.x * 128;
    const int c0  = blockIdx.y * 128;   // global output col base (0..383)

    // Load A tile (coalesced float4 per feat row)
#pragma unroll
    for (int i = 0; i < 8; i++) {
        int v   = tid + i * 256;            // 0..2047
        int row = v >> 4;                   // 16 float4 per row
        int k4  = (v & 15) * 4;
        int node = m0 + row;
        float4 a = make_float4(0.f, 0.f, 0.f, 0.f);
        if (node < N_NODES) a = *(const float4*)(feat + node * F + k4);
        As[row][k4 + 0] = a.x; As[row][k4 + 1] = a.y;
        As[row][k4 + 2] = a.z; As[row][k4 + 3] = a.w;
    }
    // Load B tile (fused weight matrix)
#pragma unroll
    for (int i = 0; i < 8; i++) {
        int v  = tid + i * 256;
        int k  = v >> 5;                    // 32 float4 per k-row
        int c4 = (v & 31) * 4;              // 0..124
        int gc = c0 + c4;
        float4 b;
        if (gc < 64) b = *(const float4*)(fc_w + k * 64 + gc);
        else         b = *(const float4*)(self_fc_w + k * 320 + (gc - 64));
        *(float4*)&Bs[k][c4] = b;
    }
    __syncthreads();

    const int tx = tid & 15, ty = tid >> 4;
    float acc[8][8] = {};
#pragma unroll
    for (int k = 0; k < 64; k++) {
        float a[8], b[8];
#pragma unroll
        for (int i = 0; i < 8; i++) a[i] = As[8 * ty + i][k];   // broadcast reads
        float4 b0 = *(const float4*)&Bs[k][8 * tx];
        float4 b1 = *(const float4*)&Bs[k][8 * tx + 4];
        b[0] = b0.x; b[1] = b0.y; b[2] = b0.z; b[3] = b0.w;
        b[4] = b1.x; b[5] = b1.y; b[6] = b1.z; b[7] = b1.w;
#pragma unroll
        for (int i = 0; i < 8; i++)
#pragma unroll
            for (int j = 0; j < 8; j++) acc[i][j] += a[i] * b[j];
    }

#pragma unroll
    for (int i = 0; i < 8; i++) {
        int node = m0 + 8 * ty + i;
        if (node >= N_NODES) continue;
#pragma unroll
        for (int jj = 0; jj < 2; jj++) {
            int gc = c0 + 8 * tx + jj * 4;
            float4 v = make_float4(acc[i][jj * 4], acc[i][jj * 4 + 1],
                                   acc[i][jj * 4 + 2], acc[i][jj * 4 + 3]);
            if (gc < 64) *(float4*)(g_z + node * F + gc) = v;
            else         *(float4*)(out + node * OUTC + (gc - 64)) = v;
        }
    }
}

// ---------------------------------------------------------------------------
// Kernel B: basis composition, packed per-lane:
//   g_attn4[(r*5+h)*32+l] = (ws[2l], ws[2l+1], wd[2l], wd[2l+1])
// where ws_f = sum_b w_comp[r,b]*aw[b, f, h], wd_f uses f+64.
// ---------------------------------------------------------------------------
__global__ void attn_comp_kernel(const float* __restrict__ aw,
                                 const float* __restrict__ w_comp)
{
    const int r = blockIdx.x;
    const int h = threadIdx.x >> 5;     // 0..4
    const int l = threadIdx.x & 31;
    float4 acc = make_float4(0.f, 0.f, 0.f, 0.f);
#pragma unroll
    for (int b = 0; b < NBASES; b++) {
        float wc = w_comp[r * NBASES + b];
        acc.x += wc * aw[(b * 128 + 2 * l) * NHEADS + h];
        acc.y += wc * aw[(b * 128 + 2 * l + 1) * NHEADS + h];
        acc.z += wc * aw[(b * 128 + 64 + 2 * l) * NHEADS + h];
        acc.w += wc * aw[(b * 128 + 64 + 2 * l + 1) * NHEADS + h];
    }
    g_attn4[(r * NHEADS + h) * 32 + l] = acc;
}

// ---------------------------------------------------------------------------
// Counting sort of edges by dst  (zero -> hist -> scan -> scatter)
// ---------------------------------------------------------------------------
__global__ void zero_cnt_kernel()
{
    int i = blockIdx.x * blockDim.x + threadIdx.x;
    if (i < N_NODES) g_cnt[i] = 0;
}

__global__ void hist_kernel(const int* __restrict__ dst)
{
    int e = blockIdx.x * blockDim.x + threadIdx.x;
    if (e < N_EDGES) atomicAdd(&g_cnt[dst[e]], 1);
}

__global__ void __launch_bounds__(1024) scan_kernel()
{
    __shared__ int warpsum[32];
    __shared__ int s_carry;
    const int tid  = threadIdx.x;
    const int lane = tid & 31;
    const int wid  = tid >> 5;
    if (tid == 0) { s_carry = 0; g_off[0] = 0; }
    __syncthreads();

    for (int base = 0; base < N_NODES; base += 1024) {
        int idx = base + tid;
        int v = (idx < N_NODES) ? g_cnt[idx] : 0;
        int x = v;
#pragma unroll
        for (int d = 1; d < 32; d <<= 1) {
            int y = __shfl_up_sync(0xffffffffu, x, d);
            if (lane >= d) x += y;
        }
        if (lane == 31) warpsum[wid] = x;
        __syncthreads();
        if (tid < 32) {
            int w = warpsum[tid];
#pragma unroll
            for (int d = 1; d < 32; d <<= 1) {
                int y = __shfl_up_sync(0xffffffffu, w, d);
                if (tid >= d) w += y;
            }
            warpsum[tid] = w;
        }
        __syncthreads();
        int pre  = (wid > 0) ? warpsum[wid - 1] : 0;
        int incl = s_carry + pre + x;
        if (idx < N_NODES) {
            g_off[idx + 1] = incl;
            g_cur[idx]     = incl - v;   // exclusive start = scatter cursor
        }
        __syncthreads();
        if (tid == 1023) s_carry = incl;
        __syncthreads();
    }
}

__global__ void scatter_kernel(const int* __restrict__ dst)
{
    int e = blockIdx.x * blockDim.x + threadIdx.x;
    if (e < N_EDGES) {
        int pos = atomicAdd(&g_cur[dst[e]], 1);
        g_eidx[pos] = e;
    }
}

// ---------------------------------------------------------------------------
// Kernel C: warp-per-dst gather. No atomics. Attention table in smem.
// ---------------------------------------------------------------------------
#define GATHER_BLOCKS 592   // 4 per SM

__global__ void __launch_bounds__(256) gather_kernel(const int* __restrict__ src,
                                                     const int* __restrict__ etype,
                                                     float* __restrict__ out)
{
    __shared__ float4 s_attn[NRELS * NHEADS * 32];   // 51.2 KB
    const int tid  = threadIdx.x;
    const int w    = tid >> 5;
    const int lane = tid & 31;

    for (int i = tid; i < NRELS * NHEADS * 32; i += 256) s_attn[i] = g_attn4[i];
    __syncthreads();

    for (int n = blockIdx.x * 8 + w; n < N_NODES; n += GATHER_BLOCKS * 8) {
        const int beg = g_off[n];
        const int end = g_off[n + 1];
        if (beg == end) continue;

        const float2 zd = *(const float2*)(g_z + n * F + 2 * lane);
        float acc[2 * NHEADS] = {};

        // 1-deep software pipeline over the e -> src -> z[src] chain
        int e_n  = g_eidx[beg];
        int s_n  = src[e_n];
        int r_n  = etype[e_n];
        float2 zs_n = *(const float2*)(g_z + s_n * F + 2 * lane);

        for (int i = beg; i < end; i++) {
            const int    r_c = r_n;
            const float2 zs  = zs_n;
            if (i + 1 < end) {
                int e2 = g_eidx[i + 1];
                s_n  = src[e2];
                r_n  = etype[e2];
                zs_n = *(const float2*)(g_z + s_n * F + 2 * lane);
            }

            float p[NHEADS];
#pragma unroll
            for (int h = 0; h < NHEADS; h++) {
                float4 wv = s_attn[(r_c * NHEADS + h) * 32 + lane];
                p[h] = zs.x * wv.x + zs.y * wv.y + zd.x * wv.z + zd.y * wv.w;
            }
#pragma unroll
            for (int d = 16; d > 0; d >>= 1)
#pragma unroll
                for (int h = 0; h < NHEADS; h++)
                    p[h] += __shfl_xor_sync(0xffffffffu, p[h], d);
#pragma unroll
            for (int h = 0; h < NHEADS; h++) {
                float v = p[h] > 0.f ? p[h] : 0.01f * p[h];
                acc[2 * h]     += v * zs.x;
                acc[2 * h + 1] += v * zs.y;
            }
        }

        float* ob = out + (long)n * OUTC + 2 * lane;
#pragma unroll
        for (int h = 0; h < NHEADS; h++) {
            float2 o = *(float2*)(ob + h * F);
            o.x += acc[2 * h];
            o.y += acc[2 * h + 1];
            *(float2*)(ob + h * F) = o;
        }
    }
}

// ---------------------------------------------------------------------------
extern "C" void kernel_launch(void* const* d_in, const int* in_sizes, int n_in,
                              void* d_out, int out_size)
{
    const float* feat      = (const float*)d_in[0];
    const int*   src       = (const int*)  d_in[1];
    const int*   dst       = (const int*)  d_in[2];
    const int*   etype     = (const int*)  d_in[3];
    const float* fc_w      = (const float*)d_in[4];
    const float* self_fc_w = (const float*)d_in[5];
    const float* aw        = (const float*)d_in[6];
    const float* w_comp    = (const float*)d_in[7];
    float* out = (float*)d_out;

    dim3 g1((N_NODES + 127) / 128, 3);
    proj_kernel<<<g1, 256>>>(feat, fc_w, self_fc_w, out);

    attn_comp_kernel<<<NRELS, NHEADS * 32>>>(aw, w_comp);

    zero_cnt_kernel<<<(N_NODES + 255) / 256, 256>>>();
    hist_kernel<<<(N_EDGES + 255) / 256, 256>>>(dst);
    scan_kernel<<<1, 1024>>>();
    scatter_kernel<<<(N_EDGES + 255) / 256, 256>>>(dst);

    gather_kernel<<<GATHER_BLOCKS, 256>>>(src, etype, out);
}